// round 8
// baseline (speedup 1.0000x reference)
#include <cuda_runtime.h>

// Problem constants (fixed by setup_inputs)
#define NB 16
#define H 768
#define W 768
#define HW (H * W)          // 589824
#define NHW (NB * HW)       // 9437184

// --- tiled gather kernels: one 1024-thread CTA per 64x64 pixel tile -------
#define TS 64                        // tile side
#define TPB 1024                     // threads per CTA (TS*TS/4)
#define TPW (W / TS)                 // 12 tiles per row
#define TILES (TPW * (H / TS))       // 144 tiles per image

// --- streaming prepass config ---------------------------------------------
#define PT 256
#define PBLKS (HW / (PT * 4))        // 576

// Ping-pong scratch for interleaved disp (float2 = (dx, dy)) — static, no alloc.
__device__ float2 g_bufA[NHW];
__device__ float2 g_bufB[NHW];

__device__ __forceinline__ int clampi(int v, int hi) {
    return min(max(v, 0), hi);
}

// ---------------------------------------------------------------------------
// Prepass: planar pred_disp [N,2,H,W] -> interleaved float2; zero num_touch;
// write the constant pred_cent b-plane (= n). Pure streaming.
// ---------------------------------------------------------------------------
__global__ __launch_bounds__(PT, 8)
void interleave(const float* __restrict__ in, float2* __restrict__ out,
                float* __restrict__ nt, float* __restrict__ pc_b) {
    const int p = (blockIdx.x * PT + threadIdx.x) * 4;
    const int n = blockIdx.y;

    const float* base = in + (size_t)n * 2 * HW;
    const float4 vx = *(const float4*)(base + p);
    const float4 vy = *(const float4*)(base + HW + p);

    float2* ob = out + (size_t)n * HW + p;
    *(float4*)(ob)     = make_float4(vx.x, vy.x, vx.y, vy.y);
    *(float4*)(ob + 2) = make_float4(vx.z, vy.z, vx.w, vy.w);

    __stcs((float4*)(nt + (size_t)n * HW + p), make_float4(0.f, 0.f, 0.f, 0.f));
    __stcs((float4*)(pc_b + (size_t)n * 3 * HW + p),
           make_float4((float)n, (float)n, (float)n, (float)n));
}

// ---------------------------------------------------------------------------
// Iterations 1,2,3: interleaved -> interleaved, 64x64 tile per CTA so the
// gather window (tile + ~48px halo, ~205KB) fits in this SM's private L1.
// ---------------------------------------------------------------------------
__global__ __launch_bounds__(TPB, 1)
void iter_mid(const float2* __restrict__ in, float2* __restrict__ out) {
    const int tile = blockIdx.x;
    const int n = blockIdx.y;
    const int x = (tile % TPW) * TS + (threadIdx.x & 15) * 4;
    const int y = (tile / TPW) * TS + (threadIdx.x >> 4);
    const int p = y * W + x;

    const float2* base = in + (size_t)n * HW;

    const float4 a = *(const float4*)(base + p);      // px 0,1
    const float4 b = *(const float4*)(base + p + 2);  // px 2,3
    float dx[4] = {a.x, a.z, b.x, b.z};
    float dy[4] = {a.y, a.w, b.y, b.w};

    int gp[4];
#pragma unroll
    for (int i = 0; i < 4; i++) {
        int cx = clampi((int)((float)(x + i) + dx[i]), W - 1);
        int cy = clampi((int)((float)y + dy[i]), H - 1);
        gp[i] = cy * W + cx;
    }

    float2 g[4];
#pragma unroll
    for (int i = 0; i < 4; i++) g[i] = __ldg(base + gp[i]);  // mostly L1 hits

    float2* ob = out + (size_t)n * HW + p;
    *(float4*)(ob)     = make_float4(dx[0] + g[0].x, dy[0] + g[0].y,
                                     dx[1] + g[1].x, dy[1] + g[1].y);
    *(float4*)(ob + 2) = make_float4(dx[2] + g[2].x, dy[2] + g[2].y,
                                     dx[3] + g[3].x, dy[3] + g[3].y);
}

// ---------------------------------------------------------------------------
// Iteration 4 (final): tiled like iter_mid. Writes planar disp, num_touch
// scatter-add, pred_cent cx/cy planes (b-plane already written by prepass).
//   d_out layout: [disp: 2*NHW][num_touch: NHW][pred_cent: 3*NHW]
// ---------------------------------------------------------------------------
__global__ __launch_bounds__(TPB, 1)
void iter_last(const float2* __restrict__ in,
               float* __restrict__ disp_out,
               float* __restrict__ nt_out,
               float* __restrict__ pc_out) {
    const int tile = blockIdx.x;
    const int n = blockIdx.y;
    const int x = (tile % TPW) * TS + (threadIdx.x & 15) * 4;
    const int y = (tile / TPW) * TS + (threadIdx.x >> 4);
    const int p = y * W + x;

    const float2* base = in + (size_t)n * HW;

    const float4 a = *(const float4*)(base + p);
    const float4 b = *(const float4*)(base + p + 2);
    float dx[4] = {a.x, a.z, b.x, b.z};
    float dy[4] = {a.y, a.w, b.y, b.w};

    int cx[4], cy[4], gp[4];
#pragma unroll
    for (int i = 0; i < 4; i++) {
        cx[i] = clampi((int)((float)(x + i) + dx[i]), W - 1);
        cy[i] = clampi((int)((float)y + dy[i]), H - 1);
        gp[i] = cy[i] * W + cx[i];
    }

    float2 g[4];
#pragma unroll
    for (int i = 0; i < 4; i++) g[i] = __ldg(base + gp[i]);

    // disp out (planar [N,2,H,W]) — streaming (never re-read)
    float* db = disp_out + (size_t)n * 2 * HW;
    __stcs((float4*)(db + p),      make_float4(dx[0] + g[0].x, dx[1] + g[1].x,
                                               dx[2] + g[2].x, dx[3] + g[3].x));
    __stcs((float4*)(db + HW + p), make_float4(dy[0] + g[0].y, dy[1] + g[1].y,
                                               dy[2] + g[2].y, dy[3] + g[3].y));

    // num_touch scatter-add (counts are small integers; exact in f32)
    float* ntb = nt_out + (size_t)n * HW;
#pragma unroll
    for (int i = 0; i < 4; i++) atomicAdd(&ntb[gp[i]], 1.0f);

    // pred_cent cx/cy planes — streaming
    float* pb = pc_out + (size_t)n * 3 * HW;
    __stcs((float4*)(pb + HW + p), make_float4((float)cx[0], (float)cx[1],
                                               (float)cx[2], (float)cx[3]));
    __stcs((float4*)(pb + 2 * HW + p), make_float4((float)cy[0], (float)cy[1],
                                                   (float)cy[2], (float)cy[3]));
}

extern "C" void kernel_launch(void* const* d_in, const int* in_sizes, int n_in,
                              void* d_out, int out_size) {
    const float* pred_disp = (const float*)d_in[0];
    float* out = (float*)d_out;

    float* disp_out = out;                      // 2*NHW
    float* nt_out   = out + (size_t)2 * NHW;    // NHW
    float* pc_out   = out + (size_t)3 * NHW;    // 3*NHW

    float2* bufA;  cudaGetSymbolAddress((void**)&bufA, g_bufA);
    float2* bufB;  cudaGetSymbolAddress((void**)&bufB, g_bufB);

    dim3 pgrid(PBLKS, NB);
    dim3 tgrid(TILES, NB);

    interleave<<<pgrid, PT>>>(pred_disp, bufA, nt_out, pc_out);  // layout + consts
    iter_mid  <<<tgrid, TPB>>>(bufA, bufB);                      // it 1
    iter_mid  <<<tgrid, TPB>>>(bufB, bufA);                      // it 2
    iter_mid  <<<tgrid, TPB>>>(bufA, bufB);                      // it 3
    iter_last <<<tgrid, TPB>>>(bufB, disp_out, nt_out, pc_out);  // it 4
}

// round 9
// speedup vs baseline: 1.1999x; 1.1999x over previous
#include <cuda_runtime.h>

// Problem constants (fixed by setup_inputs)
#define NB 16
#define H 768
#define W 768
#define HW (H * W)          // 589824
#define NHW (NB * HW)       // 9437184

// Linear mapping: each thread handles 4 consecutive pixels (768%4==0 so a
// chunk never crosses a row). 256 threads/block; HW/1024 = 576 blocks exact.
#define T 256
#define BLKS (HW / (T * 4))          // 576

// Ping-pong scratch for interleaved disp (float2 = (dx, dy)) — static, no alloc.
__device__ float2 g_bufA[NHW];
__device__ float2 g_bufB[NHW];

__device__ __forceinline__ int clampi(int v, int hi) {
    return min(max(v, 0), hi);
}

// ---------------------------------------------------------------------------
// Prepass: planar pred_disp [N,2,H,W] -> interleaved float2; zero num_touch;
// write the constant pred_cent b-plane (= n). Pure streaming.
// ---------------------------------------------------------------------------
__global__ __launch_bounds__(T, 8)
void interleave(const float* __restrict__ in, float2* __restrict__ out,
                float* __restrict__ nt, float* __restrict__ pc_b) {
    const int p = (blockIdx.x * T + threadIdx.x) * 4;
    const int n = blockIdx.y;

    const float* base = in + (size_t)n * 2 * HW;
    const float4 vx = *(const float4*)(base + p);
    const float4 vy = *(const float4*)(base + HW + p);

    float2* ob = out + (size_t)n * HW + p;
    *(float4*)(ob)     = make_float4(vx.x, vy.x, vx.y, vy.y);
    *(float4*)(ob + 2) = make_float4(vx.z, vy.z, vx.w, vy.w);

    __stcs((float4*)(nt + (size_t)n * HW + p), make_float4(0.f, 0.f, 0.f, 0.f));
    __stcs((float4*)(pc_b + (size_t)n * 3 * HW + p),
           make_float4((float)n, (float)n, (float)n, (float)n));

    cudaTriggerProgrammaticLaunchCompletion();
}

// ---------------------------------------------------------------------------
// Iterations 1,2,3: interleaved -> interleaved. PDL-synced on its producer.
// ---------------------------------------------------------------------------
__global__ __launch_bounds__(T, 8)
void iter_mid(const float2* __restrict__ in, float2* __restrict__ out) {
    const int p = (blockIdx.x * T + threadIdx.x) * 4;
    const int n = blockIdx.y;
    const int y = p / W;
    const int x = p - y * W;
    const float2* base = in + (size_t)n * HW;
    float2* ob = out + (size_t)n * HW + p;

    cudaGridDependencySynchronize();   // wait for producer's data

    const float4 a = *(const float4*)(base + p);      // px 0,1
    const float4 b = *(const float4*)(base + p + 2);  // px 2,3
    float dx[4] = {a.x, a.z, b.x, b.z};
    float dy[4] = {a.y, a.w, b.y, b.w};

    int gp[4];
#pragma unroll
    for (int i = 0; i < 4; i++) {
        int cx = clampi((int)((float)(x + i) + dx[i]), W - 1);
        int cy = clampi((int)((float)y + dy[i]), H - 1);
        gp[i] = cy * W + cx;
    }

    float2 g[4];
#pragma unroll
    for (int i = 0; i < 4; i++) g[i] = __ldg(base + gp[i]);  // independent gathers

    *(float4*)(ob)     = make_float4(dx[0] + g[0].x, dy[0] + g[0].y,
                                     dx[1] + g[1].x, dy[1] + g[1].y);
    *(float4*)(ob + 2) = make_float4(dx[2] + g[2].x, dy[2] + g[2].y,
                                     dx[3] + g[3].x, dy[3] + g[3].y);

    cudaTriggerProgrammaticLaunchCompletion();
}

// ---------------------------------------------------------------------------
// Iteration 4 (final): gather + planar disp out + num_touch scatter-add +
// pred_cent cx/cy planes (b-plane written by prepass).
//   d_out layout: [disp: 2*NHW][num_touch: NHW][pred_cent: 3*NHW]
// ---------------------------------------------------------------------------
__global__ __launch_bounds__(T, 8)
void iter_last(const float2* __restrict__ in,
               float* __restrict__ disp_out,
               float* __restrict__ nt_out,
               float* __restrict__ pc_out) {
    const int p = (blockIdx.x * T + threadIdx.x) * 4;
    const int n = blockIdx.y;
    const int y = p / W;
    const int x = p - y * W;
    const float2* base = in + (size_t)n * HW;

    cudaGridDependencySynchronize();   // wait for iter-3 data

    const float4 a = *(const float4*)(base + p);
    const float4 b = *(const float4*)(base + p + 2);
    float dx[4] = {a.x, a.z, b.x, b.z};
    float dy[4] = {a.y, a.w, b.y, b.w};

    int cx[4], cy[4], gp[4];
#pragma unroll
    for (int i = 0; i < 4; i++) {
        cx[i] = clampi((int)((float)(x + i) + dx[i]), W - 1);
        cy[i] = clampi((int)((float)y + dy[i]), H - 1);
        gp[i] = cy[i] * W + cx[i];
    }

    float2 g[4];
#pragma unroll
    for (int i = 0; i < 4; i++) g[i] = __ldg(base + gp[i]);

    // disp out (planar [N,2,H,W]) — streaming (never re-read)
    float* db = disp_out + (size_t)n * 2 * HW;
    __stcs((float4*)(db + p),      make_float4(dx[0] + g[0].x, dx[1] + g[1].x,
                                               dx[2] + g[2].x, dx[3] + g[3].x));
    __stcs((float4*)(db + HW + p), make_float4(dy[0] + g[0].y, dy[1] + g[1].y,
                                               dy[2] + g[2].y, dy[3] + g[3].y));

    // num_touch scatter-add (counts are small integers; exact in f32)
    float* ntb = nt_out + (size_t)n * HW;
#pragma unroll
    for (int i = 0; i < 4; i++) atomicAdd(&ntb[gp[i]], 1.0f);

    // pred_cent cx/cy planes — streaming
    float* pb = pc_out + (size_t)n * 3 * HW;
    __stcs((float4*)(pb + HW + p), make_float4((float)cx[0], (float)cx[1],
                                               (float)cx[2], (float)cx[3]));
    __stcs((float4*)(pb + 2 * HW + p), make_float4((float)cy[0], (float)cy[1],
                                                   (float)cy[2], (float)cy[3]));
}

// ---------------------------------------------------------------------------
// Host: launch with programmatic dependent launch so each kernel's prologue
// overlaps its producer's tail wave. Graph-capturable.
// ---------------------------------------------------------------------------
template <typename K, typename... Args>
static inline void launch_pdl(K kernel, dim3 grid, dim3 block, Args... args) {
    cudaLaunchConfig_t cfg = {};
    cfg.gridDim = grid;
    cfg.blockDim = block;
    cfg.stream = 0;
    cudaLaunchAttribute at[1];
    at[0].id = cudaLaunchAttributeProgrammaticStreamSerialization;
    at[0].val.programmaticStreamSerializationAllowed = 1;
    cfg.attrs = at;
    cfg.numAttrs = 1;
    cudaLaunchKernelEx(&cfg, kernel, args...);
}

extern "C" void kernel_launch(void* const* d_in, const int* in_sizes, int n_in,
                              void* d_out, int out_size) {
    const float* pred_disp = (const float*)d_in[0];
    float* out = (float*)d_out;

    float* disp_out = out;                      // 2*NHW
    float* nt_out   = out + (size_t)2 * NHW;    // NHW
    float* pc_out   = out + (size_t)3 * NHW;    // 3*NHW

    float2* bufA;  cudaGetSymbolAddress((void**)&bufA, g_bufA);
    float2* bufB;  cudaGetSymbolAddress((void**)&bufB, g_bufB);

    dim3 grid(BLKS, NB);

    interleave<<<grid, T>>>(pred_disp, bufA, nt_out, pc_out);       // layout+consts
    launch_pdl(iter_mid,  grid, dim3(T), (const float2*)bufA, bufB);            // it 1
    launch_pdl(iter_mid,  grid, dim3(T), (const float2*)bufB, bufA);            // it 2
    launch_pdl(iter_mid,  grid, dim3(T), (const float2*)bufA, bufB);            // it 3
    launch_pdl(iter_last, grid, dim3(T), (const float2*)bufB,
               disp_out, nt_out, pc_out);                                        // it 4
}